// round 11
// baseline (speedup 1.0000x reference)
#include <cuda_runtime.h>
#include <cuda_fp16.h>
#include <cstdint>

// Winograd F(2x2,3x3): N=16, C=128, O=128, H=W=112, pad=1
#define NB 16
#define CD 128
#define OD 128
#define HH 112
#define NT 56
#define TPI (NT*NT)            // 3136 tiles per image
#define TILES (NB*TPI)         // 50176 total tiles

// Scratch (allocation-free): U, V single fp16.
__device__ unsigned short g_Uh[16 * OD * 128];            // 512 KB U[p][o][c]
__device__ unsigned short g_Vh[(size_t)16 * TILES * 128]; // 205 MB V[p][tile][c]

__device__ __forceinline__ uint32_t smem_to_u32(const void* p) {
    uint32_t a;
    asm("{ .reg .u64 t; cvta.to.shared.u64 t, %1; cvt.u32.u64 %0, t; }" : "=r"(a) : "l"(p));
    return a;
}

// ldmatrix x4 (sm_75+)
#define LDSM4(r, addr) \
    asm volatile("ldmatrix.sync.aligned.m8n8.x4.shared.b16 {%0,%1,%2,%3}, [%4];" \
        : "=r"((r)[0]), "=r"((r)[1]), "=r"((r)[2]), "=r"((r)[3]) : "r"(addr))

// fp16 HMMA with fp32 accumulate (sm_80+)
#define MMA_F16(d, a, b) \
    asm volatile("mma.sync.aligned.m16n8k16.row.col.f32.f16.f16.f32 " \
        "{%0,%1,%2,%3},{%4,%5,%6,%7},{%8,%9},{%0,%1,%2,%3};" \
        : "+f"((d)[0]), "+f"((d)[1]), "+f"((d)[2]), "+f"((d)[3]) \
        : "r"((a)[0]), "r"((a)[1]), "r"((a)[2]), "r"((a)[3]), \
          "r"((b)[0]), "r"((b)[1]))

// cp.async (sm_80+)
#define CP16(dst, src) \
    asm volatile("cp.async.cg.shared.global [%0], [%1], 16;" :: "r"(dst), "l"(src) : "memory")
#define CP_COMMIT() asm volatile("cp.async.commit_group;" ::: "memory")
#define CP_WAIT0()  asm volatile("cp.async.wait_group 0;" ::: "memory")

// 256B rows = 16x 16B units; swizzle keeps bit3, XORs low3 with row
__device__ __forceinline__ uint32_t swz8(uint32_t u, uint32_t row) {
    return (u & 8u) | ((u ^ row) & 7u);
}

// ---------------- K1: weight transform  U = G g G^T -> fp16 ------------------
__global__ void k_wt(const float* __restrict__ w) {
    int tid = blockIdx.x * 128 + threadIdx.x;   // 16384 threads: (c,o)
    int o = tid & 127;
    int c = tid >> 7;
    const float* g = w + ((size_t)o * CD + c) * 9;
    float gm[3][3];
#pragma unroll
    for (int i = 0; i < 3; i++)
#pragma unroll
        for (int j = 0; j < 3; j++) gm[i][j] = g[i * 3 + j];

    float t[4][3];
#pragma unroll
    for (int k = 0; k < 3; k++) {
        t[0][k] = gm[0][k];
        t[1][k] = 0.5f * (gm[0][k] + gm[1][k] + gm[2][k]);
        t[2][k] = 0.5f * (gm[0][k] - gm[1][k] + gm[2][k]);
        t[3][k] = gm[2][k];
    }
#pragma unroll
    for (int i = 0; i < 4; i++) {
        float u[4];
        u[0] = t[i][0];
        u[1] = 0.5f * (t[i][0] + t[i][1] + t[i][2]);
        u[2] = 0.5f * (t[i][0] - t[i][1] + t[i][2]);
        u[3] = t[i][2];
#pragma unroll
        for (int j = 0; j < 4; j++) {
            int p = i * 4 + j;
            g_Uh[((size_t)(p * OD + o)) * 128 + c] =
                __half_as_ushort(__float2half_rn(u[j]));
        }
    }
}

// ---------------- K2: input transform -> V[p][tile][c] fp16 ------------------
__global__ void __launch_bounds__(256) k_in(const float* __restrict__ x) {
    extern __shared__ uint32_t S[];   // [32 c][16 p][32 tiles] fp16 bits = 64KB
    const int tid = threadIdx.x;
    const int lane = tid & 31;
    const int cg8 = tid >> 5;

    {
        int tile = blockIdx.x * 32 + lane;
        int n = tile / TPI;
        int r = tile - n * TPI;
        int ty = r / NT;
        int tx = r - ty * NT;
        int r0 = 2 * ty - 1, c0 = 2 * tx - 1;
        const float* xn = x + (size_t)n * CD * (HH * HH);

#pragma unroll
        for (int cs = 0; cs < 4; cs++) {
            int cl = cg8 * 4 + cs;
            int c = blockIdx.y * 32 + cl;
            const float* xp = xn + (size_t)c * (HH * HH);
            float d[4][4];
#pragma unroll
            for (int ii = 0; ii < 4; ii++) {
                int rr = r0 + ii;
                bool okr = ((unsigned)rr < HH);
#pragma unroll
                for (int jj = 0; jj < 4; jj++) {
                    int cc = c0 + jj;
                    d[ii][jj] = (okr && (unsigned)cc < HH) ? xp[rr * HH + cc] : 0.0f;
                }
            }
            float t[4][4];
#pragma unroll
            for (int j = 0; j < 4; j++) {
                t[0][j] = d[0][j] - d[2][j];
                t[1][j] = d[1][j] + d[2][j];
                t[2][j] = d[2][j] - d[1][j];
                t[3][j] = d[1][j] - d[3][j];
            }
#pragma unroll
            for (int i = 0; i < 4; i++) {
                float v0 = t[i][0] - t[i][2];
                float v1 = t[i][1] + t[i][2];
                float v2 = t[i][2] - t[i][1];
                float v3 = t[i][1] - t[i][3];
                S[(cl * 16 + (i * 4 + 0)) * 32 + lane] =
                    (uint32_t)__half_as_ushort(__float2half_rn(v0));
                S[(cl * 16 + (i * 4 + 1)) * 32 + lane] =
                    (uint32_t)__half_as_ushort(__float2half_rn(v1));
                S[(cl * 16 + (i * 4 + 2)) * 32 + lane] =
                    (uint32_t)__half_as_ushort(__float2half_rn(v2));
                S[(cl * 16 + (i * 4 + 3)) * 32 + lane] =
                    (uint32_t)__half_as_ushort(__float2half_rn(v3));
            }
        }
    }
    __syncthreads();

    // Pass 2: each thread emits one (p, tile) 32-channel chunk: 64B fp16
#pragma unroll
    for (int it = 0; it < 2; it++) {
        int q = it * 256 + tid;      // 512 = 16p * 32tiles
        int p = q >> 5;
        int tl = q & 31;
        int tile = blockIdx.x * 32 + tl;

        uint32_t hp[16];
#pragma unroll
        for (int c2 = 0; c2 < 16; c2++) {
            uint32_t u0 = S[((2 * c2) * 16 + p) * 32 + tl];
            uint32_t u1 = S[((2 * c2 + 1) * 16 + p) * 32 + tl];
            hp[c2] = (u0 & 0xffffu) | (u1 << 16);
        }
        unsigned short* vb = g_Vh + ((size_t)p * TILES + tile) * 128 + blockIdx.y * 32;
#pragma unroll
        for (int i = 0; i < 4; i++) *(uint4*)(vb + i * 8) = *((uint4*)hp + i);
    }
}

// ---------------- K3: fused GEMM + output transform ---------------------------
// CTA: o=128 x tiles=64, 512 threads (16 warps = 4 o-groups x 4 t-groups,
// warp tile 32o x 16t). Per p: M[p] = U·V (single fp16 MMA), fold into Y.
#define STG_BYTES 49152            // A 32KB + B 16KB
#define FUSE_SMEM (2 * STG_BYTES)  // 96 KB

__global__ void __launch_bounds__(512, 1) k_fused(const float* __restrict__ bias,
                                                  float* __restrict__ y) {
    extern __shared__ char sm[];
    const uint32_t base = smem_to_u32(sm);
    const int tid = threadIdx.x;
    const int lane = tid & 31;
    const int wid = tid >> 5;
    const int jb = blockIdx.x * 64;
    const int o0 = (wid & 3) * 32;    // 4 o-groups
    const int n0 = (wid >> 2) * 16;   // 4 t-groups

    // stage p=0 into buffer 0
    {
        const uint4* gA = (const uint4*)g_Uh;
#pragma unroll
        for (int i = 0; i < 4; i++) {
            int g = i * 512 + tid;                 // 2048 chunks (32KB)
            uint32_t row = (uint32_t)g >> 4, u = (uint32_t)g & 15;
            CP16(base + row * 256 + swz8(u, row) * 16, gA + g);
        }
        const uint4* gB = (const uint4*)(g_Vh + (size_t)jb * 128);
#pragma unroll
        for (int i = 0; i < 2; i++) {
            int g = i * 512 + tid;                 // 1024 chunks (16KB)
            uint32_t row = (uint32_t)g >> 4, u = (uint32_t)g & 15;
            CP16(base + 32768 + row * 256 + swz8(u, row) * 16, gB + g);
        }
        CP_COMMIT();
    }

    float accY[2][2][2][2][4];   // [a][b][m][nf][j] = 64 regs
#pragma unroll
    for (int a = 0; a < 2; a++)
#pragma unroll
        for (int b = 0; b < 2; b++)
#pragma unroll
            for (int m = 0; m < 2; m++)
#pragma unroll
                for (int nf = 0; nf < 2; nf++)
#pragma unroll
                    for (int j = 0; j < 4; j++) accY[a][b][m][nf][j] = 0.0f;

    const uint32_t rA = (uint32_t)(o0 + (lane & 15));
    const uint32_t uA = (uint32_t)(lane >> 4);
    const uint32_t rB = (uint32_t)(n0 + (lane & 7) + ((lane & 16) >> 1));
    const uint32_t uB = (uint32_t)((lane >> 3) & 1);

    const float AT0[4] = {1.f, 1.f, 1.f, 0.f};
    const float AT1[4] = {0.f, 1.f, -1.f, -1.f};

#pragma unroll
    for (int p = 0; p < 16; p++) {
        CP_WAIT0();
        __syncthreads();

        if (p < 15) {   // stage p+1 into the other buffer
            uint32_t nb = base + (uint32_t)((p + 1) & 1) * STG_BYTES;
            const uint4* gA = (const uint4*)(g_Uh + (size_t)(p + 1) * OD * 128);
#pragma unroll
            for (int i = 0; i < 4; i++) {
                int g = i * 512 + tid;
                uint32_t row = (uint32_t)g >> 4, u = (uint32_t)g & 15;
                CP16(nb + row * 256 + swz8(u, row) * 16, gA + g);
            }
            const uint4* gB = (const uint4*)(g_Vh + ((size_t)(p + 1) * TILES + jb) * 128);
#pragma unroll
            for (int i = 0; i < 2; i++) {
                int g = i * 512 + tid;
                uint32_t row = (uint32_t)g >> 4, u = (uint32_t)g & 15;
                CP16(nb + 32768 + row * 256 + swz8(u, row) * 16, gB + g);
            }
            CP_COMMIT();
        }

        const uint32_t aB = base + (uint32_t)(p & 1) * STG_BYTES;
        const uint32_t bB = aB + 32768;

        float macc[2][2][4];
#pragma unroll
        for (int m = 0; m < 2; m++)
#pragma unroll
            for (int nf = 0; nf < 2; nf++)
#pragma unroll
                for (int j = 0; j < 4; j++) macc[m][nf][j] = 0.0f;

#pragma unroll
        for (int kc = 0; kc < 8; kc++) {
            uint32_t ah[2][4], bh[2][2];
#pragma unroll
            for (int m = 0; m < 2; m++) {
                uint32_t r = rA + m * 16;
                uint32_t u = 2 * kc + uA;
                LDSM4(ah[m], aB + r * 256 + (swz8(u, r) << 4));
            }
            {
                uint32_t u = 2 * kc + uB;
                uint32_t t[4];
                LDSM4(t, bB + rB * 256 + (swz8(u, rB) << 4));
                bh[0][0] = t[0]; bh[0][1] = t[1];
                bh[1][0] = t[2]; bh[1][1] = t[3];
            }
#pragma unroll
            for (int m = 0; m < 2; m++)
#pragma unroll
                for (int nf = 0; nf < 2; nf++)
                    MMA_F16(macc[m][nf], ah[m], bh[nf]);
        }

        // fold M[p] into Y_ab with compile-time ±1 coefficients (p unrolled)
        const int pi = p >> 2, pj = p & 3;
#pragma unroll
        for (int a = 0; a < 2; a++) {
            const float wa = (a == 0) ? AT0[pi] : AT1[pi];
#pragma unroll
            for (int b = 0; b < 2; b++) {
                const float wb = (b == 0) ? AT0[pj] : AT1[pj];
                const float c = wa * wb;
                if (c != 0.0f) {
#pragma unroll
                    for (int m = 0; m < 2; m++)
#pragma unroll
                        for (int nf = 0; nf < 2; nf++)
#pragma unroll
                            for (int j = 0; j < 4; j++)
                                accY[a][b][m][nf][j] = fmaf(c, macc[m][nf][j],
                                                            accY[a][b][m][nf][j]);
                }
            }
        }
        __syncthreads();
    }

    // Epilogue: bias + direct Y writes
#pragma unroll
    for (int m = 0; m < 2; m++) {
#pragma unroll
        for (int h = 0; h < 2; h++) {
            int o = o0 + m * 16 + (lane >> 2) + h * 8;
            float bv = bias[o];
#pragma unroll
            for (int nf = 0; nf < 2; nf++) {
#pragma unroll
                for (int d = 0; d < 2; d++) {
                    int t = jb + n0 + nf * 8 + (lane & 3) * 2 + d;
                    int n = t / TPI;
                    int r = t - n * TPI;
                    int ty = r / NT;
                    int tx = r - ty * NT;
                    float* yp = y + ((size_t)(n * OD + o) * HH + 2 * ty) * HH + 2 * tx;
                    int j = 2 * h + d;
                    float2 v0 = make_float2(accY[0][0][m][nf][j] + bv,
                                            accY[0][1][m][nf][j] + bv);
                    float2 v1 = make_float2(accY[1][0][m][nf][j] + bv,
                                            accY[1][1][m][nf][j] + bv);
                    *(float2*)yp = v0;
                    *(float2*)(yp + HH) = v1;
                }
            }
        }
    }
}

// ---------------- launch --------------------------------------------------------
extern "C" void kernel_launch(void* const* d_in, const int* in_sizes, int n_in,
                              void* d_out, int out_size) {
    const float* x = (const float*)d_in[0];
    const float* w = (const float*)d_in[1];
    const float* bias = (const float*)d_in[2];
    float* y = (float*)d_out;

    cudaFuncSetAttribute(k_in, cudaFuncAttributeMaxDynamicSharedMemorySize, 65536);
    cudaFuncSetAttribute(k_fused, cudaFuncAttributeMaxDynamicSharedMemorySize, FUSE_SMEM);

    k_wt<<<128, 128>>>(w);
    dim3 gi(TILES / 32, 4);                 // 1568 x 4
    k_in<<<gi, 256, 65536>>>(x);
    k_fused<<<TILES / 64, 512, FUSE_SMEM>>>(bias, y);   // 784 CTAs
}

// round 12
// speedup vs baseline: 1.0288x; 1.0288x over previous
#include <cuda_runtime.h>
#include <cuda_fp16.h>
#include <cstdint>

// Winograd F(2x2,3x3): N=16, C=128, O=128, H=W=112, pad=1
#define NB 16
#define CD 128
#define OD 128
#define HH 112
#define NT 56
#define TPI (NT*NT)            // 3136 tiles per image
#define TILES (NB*TPI)         // 50176 total tiles

// Scratch (allocation-free): U, V single fp16.
__device__ unsigned short g_Uh[16 * OD * 128];            // 512 KB U[p][o][c]
__device__ unsigned short g_Vh[(size_t)16 * TILES * 128]; // 205 MB V[p][tile][c]

__device__ __forceinline__ uint32_t smem_to_u32(const void* p) {
    uint32_t a;
    asm("{ .reg .u64 t; cvta.to.shared.u64 t, %1; cvt.u32.u64 %0, t; }" : "=r"(a) : "l"(p));
    return a;
}

// ldmatrix x4 (sm_75+)
#define LDSM4(r, addr) \
    asm volatile("ldmatrix.sync.aligned.m8n8.x4.shared.b16 {%0,%1,%2,%3}, [%4];" \
        : "=r"((r)[0]), "=r"((r)[1]), "=r"((r)[2]), "=r"((r)[3]) : "r"(addr))

// fp16 HMMA with fp32 accumulate (sm_80+)
#define MMA_F16(d, a, b) \
    asm volatile("mma.sync.aligned.m16n8k16.row.col.f32.f16.f16.f32 " \
        "{%0,%1,%2,%3},{%4,%5,%6,%7},{%8,%9},{%0,%1,%2,%3};" \
        : "+f"((d)[0]), "+f"((d)[1]), "+f"((d)[2]), "+f"((d)[3]) \
        : "r"((a)[0]), "r"((a)[1]), "r"((a)[2]), "r"((a)[3]), \
          "r"((b)[0]), "r"((b)[1]))

// cp.async (sm_80+)
#define CP16(dst, src) \
    asm volatile("cp.async.cg.shared.global [%0], [%1], 16;" :: "r"(dst), "l"(src) : "memory")
#define CP_COMMIT() asm volatile("cp.async.commit_group;" ::: "memory")
#define CP_WAIT0()  asm volatile("cp.async.wait_group 0;" ::: "memory")

// 256B rows = 16x 16B units; swizzle keeps bit3, XORs low3 with row
__device__ __forceinline__ uint32_t swz8(uint32_t u, uint32_t row) {
    return (u & 8u) | ((u ^ row) & 7u);
}

// ---------------- K1: weight transform  U = G g G^T -> fp16 ------------------
__global__ void k_wt(const float* __restrict__ w) {
    int tid = blockIdx.x * 128 + threadIdx.x;   // 16384 threads: (c,o)
    int o = tid & 127;
    int c = tid >> 7;
    const float* g = w + ((size_t)o * CD + c) * 9;
    float gm[3][3];
#pragma unroll
    for (int i = 0; i < 3; i++)
#pragma unroll
        for (int j = 0; j < 3; j++) gm[i][j] = g[i * 3 + j];

    float t[4][3];
#pragma unroll
    for (int k = 0; k < 3; k++) {
        t[0][k] = gm[0][k];
        t[1][k] = 0.5f * (gm[0][k] + gm[1][k] + gm[2][k]);
        t[2][k] = 0.5f * (gm[0][k] - gm[1][k] + gm[2][k]);
        t[3][k] = gm[2][k];
    }
#pragma unroll
    for (int i = 0; i < 4; i++) {
        float u[4];
        u[0] = t[i][0];
        u[1] = 0.5f * (t[i][0] + t[i][1] + t[i][2]);
        u[2] = 0.5f * (t[i][0] - t[i][1] + t[i][2]);
        u[3] = t[i][2];
#pragma unroll
        for (int j = 0; j < 4; j++) {
            int p = i * 4 + j;
            g_Uh[((size_t)(p * OD + o)) * 128 + c] =
                __half_as_ushort(__float2half_rn(u[j]));
        }
    }
}

// ---------------- K2: input transform -> V[p][tile][c] fp16 ------------------
__global__ void __launch_bounds__(256) k_in(const float* __restrict__ x) {
    extern __shared__ uint32_t S[];   // [32 c][16 p][32 tiles] fp16 bits = 64KB
    const int tid = threadIdx.x;
    const int lane = tid & 31;
    const int cg8 = tid >> 5;

    {
        int tile = blockIdx.x * 32 + lane;
        int n = tile / TPI;
        int r = tile - n * TPI;
        int ty = r / NT;
        int tx = r - ty * NT;
        int r0 = 2 * ty - 1, c0 = 2 * tx - 1;
        const float* xn = x + (size_t)n * CD * (HH * HH);

#pragma unroll
        for (int cs = 0; cs < 4; cs++) {
            int cl = cg8 * 4 + cs;
            int c = blockIdx.y * 32 + cl;
            const float* xp = xn + (size_t)c * (HH * HH);
            float d[4][4];
#pragma unroll
            for (int ii = 0; ii < 4; ii++) {
                int rr = r0 + ii;
                bool okr = ((unsigned)rr < HH);
#pragma unroll
                for (int jj = 0; jj < 4; jj++) {
                    int cc = c0 + jj;
                    d[ii][jj] = (okr && (unsigned)cc < HH) ? xp[rr * HH + cc] : 0.0f;
                }
            }
            float t[4][4];
#pragma unroll
            for (int j = 0; j < 4; j++) {
                t[0][j] = d[0][j] - d[2][j];
                t[1][j] = d[1][j] + d[2][j];
                t[2][j] = d[2][j] - d[1][j];
                t[3][j] = d[1][j] - d[3][j];
            }
#pragma unroll
            for (int i = 0; i < 4; i++) {
                float v0 = t[i][0] - t[i][2];
                float v1 = t[i][1] + t[i][2];
                float v2 = t[i][2] - t[i][1];
                float v3 = t[i][1] - t[i][3];
                S[(cl * 16 + (i * 4 + 0)) * 32 + lane] =
                    (uint32_t)__half_as_ushort(__float2half_rn(v0));
                S[(cl * 16 + (i * 4 + 1)) * 32 + lane] =
                    (uint32_t)__half_as_ushort(__float2half_rn(v1));
                S[(cl * 16 + (i * 4 + 2)) * 32 + lane] =
                    (uint32_t)__half_as_ushort(__float2half_rn(v2));
                S[(cl * 16 + (i * 4 + 3)) * 32 + lane] =
                    (uint32_t)__half_as_ushort(__float2half_rn(v3));
            }
        }
    }
    __syncthreads();

    // Pass 2: each thread emits one (p, tile) 32-channel chunk: 64B fp16
#pragma unroll
    for (int it = 0; it < 2; it++) {
        int q = it * 256 + tid;      // 512 = 16p * 32tiles
        int p = q >> 5;
        int tl = q & 31;
        int tile = blockIdx.x * 32 + tl;

        uint32_t hp[16];
#pragma unroll
        for (int c2 = 0; c2 < 16; c2++) {
            uint32_t u0 = S[((2 * c2) * 16 + p) * 32 + tl];
            uint32_t u1 = S[((2 * c2 + 1) * 16 + p) * 32 + tl];
            hp[c2] = (u0 & 0xffffu) | (u1 << 16);
        }
        unsigned short* vb = g_Vh + ((size_t)p * TILES + tile) * 128 + blockIdx.y * 32;
#pragma unroll
        for (int i = 0; i < 4; i++) *(uint4*)(vb + i * 8) = *((uint4*)hp + i);
    }
}

// ---------------- K3: fused GEMM + output transform ---------------------------
// CTA: o=128 x tiles=32, 256 threads (8 warps = 4 o-groups x 2 t-groups,
// warp tile 32o x 16t). 2 CTAs/SM co-resident: independent barriers keep the
// tensor pipe fed during each other's sync/fold phases.
#define STG_BYTES 40960            // A 32KB + B 8KB
#define FUSE_SMEM (2 * STG_BYTES)  // 80 KB -> 2 CTAs/SM

__global__ void __launch_bounds__(256, 2) k_fused(const float* __restrict__ bias,
                                                  float* __restrict__ y) {
    extern __shared__ char sm[];
    const uint32_t base = smem_to_u32(sm);
    const int tid = threadIdx.x;
    const int lane = tid & 31;
    const int wid = tid >> 5;
    const int jb = blockIdx.x * 32;
    const int o0 = (wid & 3) * 32;    // 4 o-groups
    const int n0 = (wid >> 2) * 16;   // 2 t-groups

    // stage p=0 into buffer 0
    {
        const uint4* gA = (const uint4*)g_Uh;
#pragma unroll
        for (int i = 0; i < 8; i++) {
            int g = i * 256 + tid;                 // 2048 chunks (32KB)
            uint32_t row = (uint32_t)g >> 4, u = (uint32_t)g & 15;
            CP16(base + row * 256 + swz8(u, row) * 16, gA + g);
        }
        const uint4* gB = (const uint4*)(g_Vh + (size_t)jb * 128);
#pragma unroll
        for (int i = 0; i < 2; i++) {
            int g = i * 256 + tid;                 // 512 chunks (8KB)
            uint32_t row = (uint32_t)g >> 4, u = (uint32_t)g & 15;
            CP16(base + 32768 + row * 256 + swz8(u, row) * 16, gB + g);
        }
        CP_COMMIT();
    }

    float accY[2][2][2][2][4];   // [a][b][m][nf][j] = 64 regs
#pragma unroll
    for (int a = 0; a < 2; a++)
#pragma unroll
        for (int b = 0; b < 2; b++)
#pragma unroll
            for (int m = 0; m < 2; m++)
#pragma unroll
                for (int nf = 0; nf < 2; nf++)
#pragma unroll
                    for (int j = 0; j < 4; j++) accY[a][b][m][nf][j] = 0.0f;

    const uint32_t rA = (uint32_t)(o0 + (lane & 15));
    const uint32_t uA = (uint32_t)(lane >> 4);
    const uint32_t rB = (uint32_t)(n0 + (lane & 7) + ((lane & 16) >> 1));
    const uint32_t uB = (uint32_t)((lane >> 3) & 1);

    const float AT0[4] = {1.f, 1.f, 1.f, 0.f};
    const float AT1[4] = {0.f, 1.f, -1.f, -1.f};

#pragma unroll
    for (int p = 0; p < 16; p++) {
        CP_WAIT0();
        __syncthreads();

        if (p < 15) {   // stage p+1 into the other buffer
            uint32_t nb = base + (uint32_t)((p + 1) & 1) * STG_BYTES;
            const uint4* gA = (const uint4*)(g_Uh + (size_t)(p + 1) * OD * 128);
#pragma unroll
            for (int i = 0; i < 8; i++) {
                int g = i * 256 + tid;
                uint32_t row = (uint32_t)g >> 4, u = (uint32_t)g & 15;
                CP16(nb + row * 256 + swz8(u, row) * 16, gA + g);
            }
            const uint4* gB = (const uint4*)(g_Vh + ((size_t)(p + 1) * TILES + jb) * 128);
#pragma unroll
            for (int i = 0; i < 2; i++) {
                int g = i * 256 + tid;
                uint32_t row = (uint32_t)g >> 4, u = (uint32_t)g & 15;
                CP16(nb + 32768 + row * 256 + swz8(u, row) * 16, gB + g);
            }
            CP_COMMIT();
        }

        const uint32_t aB = base + (uint32_t)(p & 1) * STG_BYTES;
        const uint32_t bB = aB + 32768;

        float macc[2][2][4];
#pragma unroll
        for (int m = 0; m < 2; m++)
#pragma unroll
            for (int nf = 0; nf < 2; nf++)
#pragma unroll
                for (int j = 0; j < 4; j++) macc[m][nf][j] = 0.0f;

#pragma unroll
        for (int kc = 0; kc < 8; kc++) {
            uint32_t ah[2][4], bh[2][2];
#pragma unroll
            for (int m = 0; m < 2; m++) {
                uint32_t r = rA + m * 16;
                uint32_t u = 2 * kc + uA;
                LDSM4(ah[m], aB + r * 256 + (swz8(u, r) << 4));
            }
            {
                uint32_t u = 2 * kc + uB;
                uint32_t t[4];
                LDSM4(t, bB + rB * 256 + (swz8(u, rB) << 4));
                bh[0][0] = t[0]; bh[0][1] = t[1];
                bh[1][0] = t[2]; bh[1][1] = t[3];
            }
#pragma unroll
            for (int m = 0; m < 2; m++)
#pragma unroll
                for (int nf = 0; nf < 2; nf++)
                    MMA_F16(macc[m][nf], ah[m], bh[nf]);
        }

        // fold M[p] into Y_ab with compile-time ±1 coefficients (p unrolled)
        const int pi = p >> 2, pj = p & 3;
#pragma unroll
        for (int a = 0; a < 2; a++) {
            const float wa = (a == 0) ? AT0[pi] : AT1[pi];
#pragma unroll
            for (int b = 0; b < 2; b++) {
                const float wb = (b == 0) ? AT0[pj] : AT1[pj];
                const float c = wa * wb;
                if (c != 0.0f) {
#pragma unroll
                    for (int m = 0; m < 2; m++)
#pragma unroll
                        for (int nf = 0; nf < 2; nf++)
#pragma unroll
                            for (int j = 0; j < 4; j++)
                                accY[a][b][m][nf][j] = fmaf(c, macc[m][nf][j],
                                                            accY[a][b][m][nf][j]);
                }
            }
        }
        __syncthreads();
    }

    // Epilogue: bias + direct Y writes
#pragma unroll
    for (int m = 0; m < 2; m++) {
#pragma unroll
        for (int h = 0; h < 2; h++) {
            int o = o0 + m * 16 + (lane >> 2) + h * 8;
            float bv = bias[o];
#pragma unroll
            for (int nf = 0; nf < 2; nf++) {
#pragma unroll
                for (int d = 0; d < 2; d++) {
                    int t = jb + n0 + nf * 8 + (lane & 3) * 2 + d;
                    int n = t / TPI;
                    int r = t - n * TPI;
                    int ty = r / NT;
                    int tx = r - ty * NT;
                    float* yp = y + ((size_t)(n * OD + o) * HH + 2 * ty) * HH + 2 * tx;
                    int j = 2 * h + d;
                    float2 v0 = make_float2(accY[0][0][m][nf][j] + bv,
                                            accY[0][1][m][nf][j] + bv);
                    float2 v1 = make_float2(accY[1][0][m][nf][j] + bv,
                                            accY[1][1][m][nf][j] + bv);
                    *(float2*)yp = v0;
                    *(float2*)(yp + HH) = v1;
                }
            }
        }
    }
}

// ---------------- launch --------------------------------------------------------
extern "C" void kernel_launch(void* const* d_in, const int* in_sizes, int n_in,
                              void* d_out, int out_size) {
    const float* x = (const float*)d_in[0];
    const float* w = (const float*)d_in[1];
    const float* bias = (const float*)d_in[2];
    float* y = (float*)d_out;

    cudaFuncSetAttribute(k_in, cudaFuncAttributeMaxDynamicSharedMemorySize, 65536);
    cudaFuncSetAttribute(k_fused, cudaFuncAttributeMaxDynamicSharedMemorySize, FUSE_SMEM);

    k_wt<<<128, 128>>>(w);
    dim3 gi(TILES / 32, 4);                 // 1568 x 4
    k_in<<<gi, 256, 65536>>>(x);
    k_fused<<<TILES / 32, 256, FUSE_SMEM>>>(bias, y);   // 1568 CTAs
}

// round 13
// speedup vs baseline: 1.2497x; 1.2147x over previous
#include <cuda_runtime.h>
#include <cuda_fp16.h>
#include <cstdint>

// Winograd F(2x2,3x3): N=16, C=128, O=128, H=W=112, pad=1
#define NB 16
#define CD 128
#define OD 128
#define HH 112
#define NT 56
#define TPI (NT*NT)            // 3136 tiles per image
#define TILES (NB*TPI)         // 50176 total tiles

// Scratch (allocation-free): U fp16 only. V lives in SMEM now.
__device__ unsigned short g_Uh[16 * OD * 128];            // 512 KB U[p][o][c]

__device__ __forceinline__ uint32_t smem_to_u32(const void* p) {
    uint32_t a;
    asm("{ .reg .u64 t; cvta.to.shared.u64 t, %1; cvt.u32.u64 %0, t; }" : "=r"(a) : "l"(p));
    return a;
}

// ldmatrix x4 (sm_75+)
#define LDSM4(r, addr) \
    asm volatile("ldmatrix.sync.aligned.m8n8.x4.shared.b16 {%0,%1,%2,%3}, [%4];" \
        : "=r"((r)[0]), "=r"((r)[1]), "=r"((r)[2]), "=r"((r)[3]) : "r"(addr))

// fp16 HMMA with fp32 accumulate (sm_80+)
#define MMA_F16(d, a, b) \
    asm volatile("mma.sync.aligned.m16n8k16.row.col.f32.f16.f16.f32 " \
        "{%0,%1,%2,%3},{%4,%5,%6,%7},{%8,%9},{%0,%1,%2,%3};" \
        : "+f"((d)[0]), "+f"((d)[1]), "+f"((d)[2]), "+f"((d)[3]) \
        : "r"((a)[0]), "r"((a)[1]), "r"((a)[2]), "r"((a)[3]), \
          "r"((b)[0]), "r"((b)[1]))

// cp.async (sm_80+)
#define CP16(dst, src) \
    asm volatile("cp.async.cg.shared.global [%0], [%1], 16;" :: "r"(dst), "l"(src) : "memory")
#define CP_COMMIT() asm volatile("cp.async.commit_group;" ::: "memory")
#define CP_WAIT0()  asm volatile("cp.async.wait_group 0;" ::: "memory")

// 256B rows = 16x 16B units; swizzle keeps bit3, XORs low3 with row
__device__ __forceinline__ uint32_t swz8(uint32_t u, uint32_t row) {
    return (u & 8u) | ((u ^ row) & 7u);
}

// ---------------- K1: weight transform  U = G g G^T -> fp16 ------------------
__global__ void k_wt(const float* __restrict__ w) {
    int tid = blockIdx.x * 128 + threadIdx.x;   // 16384 threads: (c,o)
    int o = tid & 127;
    int c = tid >> 7;
    const float* g = w + ((size_t)o * CD + c) * 9;
    float gm[3][3];
#pragma unroll
    for (int i = 0; i < 3; i++)
#pragma unroll
        for (int j = 0; j < 3; j++) gm[i][j] = g[i * 3 + j];

    float t[4][3];
#pragma unroll
    for (int k = 0; k < 3; k++) {
        t[0][k] = gm[0][k];
        t[1][k] = 0.5f * (gm[0][k] + gm[1][k] + gm[2][k]);
        t[2][k] = 0.5f * (gm[0][k] - gm[1][k] + gm[2][k]);
        t[3][k] = gm[2][k];
    }
#pragma unroll
    for (int i = 0; i < 4; i++) {
        float u[4];
        u[0] = t[i][0];
        u[1] = 0.5f * (t[i][0] + t[i][1] + t[i][2]);
        u[2] = 0.5f * (t[i][0] - t[i][1] + t[i][2]);
        u[3] = t[i][2];
#pragma unroll
        for (int j = 0; j < 4; j++) {
            int p = i * 4 + j;
            g_Uh[((size_t)(p * OD + o)) * 128 + c] =
                __half_as_ushort(__float2half_rn(u[j]));
        }
    }
}

// ---------------- K2: fully fused transform + GEMM + output -------------------
// CTA: o=128 x tiles=32, 256 threads (8 warps: 4 o-groups x 2 t-groups).
// Phase 1: compute V = BT d BT^T for all 16 p into SMEM (fp16, swizzled).
// Phase 2: loop p: M[p] = U[p]·V[p] (single fp16 MMA), fold into Y (AT coeffs).
// SMEM: A double-buffer 2x32KB @ 0, V 16 p-planes x 8KB @ 64KB. Total 192KB.
#define A_STG 32768
#define V_OFF 65536
#define FUSE_SMEM (V_OFF + 16 * 8192)   // 192 KB

__global__ void __launch_bounds__(256, 1) k_fused(const float* __restrict__ x,
                                                  const float* __restrict__ bias,
                                                  float* __restrict__ y) {
    extern __shared__ char sm[];
    const uint32_t base = smem_to_u32(sm);
    const int tid = threadIdx.x;
    const int lane = tid & 31;
    const int wid = tid >> 5;
    const int jb = blockIdx.x * 32;
    const int o0 = (wid & 3) * 32;    // 4 o-groups
    const int n0 = (wid >> 2) * 16;   // 2 t-groups

    // kick off A(p=0) staging; overlaps with the transform phase
    {
        const uint4* gA = (const uint4*)g_Uh;
#pragma unroll
        for (int i = 0; i < 8; i++) {
            int g = i * 256 + tid;                 // 2048 chunks (32KB)
            uint32_t row = (uint32_t)g >> 4, u = (uint32_t)g & 15;
            CP16(base + row * 256 + swz8(u, row) * 16, gA + g);
        }
        CP_COMMIT();
    }

    // ---- Phase 1: input transform into SMEM V[p][tile][c] fp16 ----
    // 2048 (c2, tl) tasks: c2 = channel pair 0..63, tl = tile 0..31.
    // Warp-uniform c2, lane = tl -> coalesced x reads.
#pragma unroll 1
    for (int it = 0; it < 8; it++) {
        int c2 = it * 8 + wid;       // 0..63
        int tl = lane;
        int tile = jb + tl;
        int n = tile / TPI;
        int r = tile - n * TPI;
        int ty = r / NT;
        int tx = r - ty * NT;
        int r0 = 2 * ty - 1, c0 = 2 * tx - 1;

        unsigned short h[2][16];
#pragma unroll
        for (int cc = 0; cc < 2; cc++) {
            int c = 2 * c2 + cc;
            const float* xp = x + ((size_t)(n * CD + c)) * (HH * HH);
            float d[4][4];
#pragma unroll
            for (int ii = 0; ii < 4; ii++) {
                int rr = r0 + ii;
                bool okr = ((unsigned)rr < HH);
#pragma unroll
                for (int jj = 0; jj < 4; jj++) {
                    int ccol = c0 + jj;
                    d[ii][jj] = (okr && (unsigned)ccol < HH) ? xp[rr * HH + ccol] : 0.0f;
                }
            }
            float t[4][4];
#pragma unroll
            for (int j = 0; j < 4; j++) {
                t[0][j] = d[0][j] - d[2][j];
                t[1][j] = d[1][j] + d[2][j];
                t[2][j] = d[2][j] - d[1][j];
                t[3][j] = d[1][j] - d[3][j];
            }
#pragma unroll
            for (int i = 0; i < 4; i++) {
                float v0 = t[i][0] - t[i][2];
                float v1 = t[i][1] + t[i][2];
                float v2 = t[i][2] - t[i][1];
                float v3 = t[i][1] - t[i][3];
                h[cc][i * 4 + 0] = __half_as_ushort(__float2half_rn(v0));
                h[cc][i * 4 + 1] = __half_as_ushort(__float2half_rn(v1));
                h[cc][i * 4 + 2] = __half_as_ushort(__float2half_rn(v2));
                h[cc][i * 4 + 3] = __half_as_ushort(__float2half_rn(v3));
            }
        }
        // write 16 p-planes: V[p][tl][c2 pair] (same layout the GEMM B expects)
        uint32_t woff = (uint32_t)tl * 256 + swz8((uint32_t)c2 >> 2, (uint32_t)tl) * 16
                        + ((uint32_t)c2 & 3) * 4;
#pragma unroll
        for (int p = 0; p < 16; p++) {
            uint32_t pk = (uint32_t)h[0][p] | ((uint32_t)h[1][p] << 16);
            *(uint32_t*)(sm + V_OFF + p * 8192 + woff) = pk;
        }
    }
    __syncthreads();

    // ---- Phase 2: GEMM + output-transform fold ----
    float accY[2][2][2][2][4];   // [a][b][m][nf][j] = 64 regs
#pragma unroll
    for (int a = 0; a < 2; a++)
#pragma unroll
        for (int b = 0; b < 2; b++)
#pragma unroll
            for (int m = 0; m < 2; m++)
#pragma unroll
                for (int nf = 0; nf < 2; nf++)
#pragma unroll
                    for (int j = 0; j < 4; j++) accY[a][b][m][nf][j] = 0.0f;

    const uint32_t rA = (uint32_t)(o0 + (lane & 15));
    const uint32_t uA = (uint32_t)(lane >> 4);
    const uint32_t rB = (uint32_t)(n0 + (lane & 7) + ((lane & 16) >> 1));
    const uint32_t uB = (uint32_t)((lane >> 3) & 1);

    const float AT0[4] = {1.f, 1.f, 1.f, 0.f};
    const float AT1[4] = {0.f, 1.f, -1.f, -1.f};

#pragma unroll
    for (int p = 0; p < 16; p++) {
        CP_WAIT0();
        __syncthreads();

        if (p < 15) {   // stage A(p+1) into the other buffer
            uint32_t nb = base + (uint32_t)((p + 1) & 1) * A_STG;
            const uint4* gA = (const uint4*)(g_Uh + (size_t)(p + 1) * OD * 128);
#pragma unroll
            for (int i = 0; i < 8; i++) {
                int g = i * 256 + tid;
                uint32_t row = (uint32_t)g >> 4, u = (uint32_t)g & 15;
                CP16(nb + row * 256 + swz8(u, row) * 16, gA + g);
            }
            CP_COMMIT();
        }

        const uint32_t aB = base + (uint32_t)(p & 1) * A_STG;
        const uint32_t bB = base + V_OFF + (uint32_t)p * 8192;

        float macc[2][2][4];
#pragma unroll
        for (int m = 0; m < 2; m++)
#pragma unroll
            for (int nf = 0; nf < 2; nf++)
#pragma unroll
                for (int j = 0; j < 4; j++) macc[m][nf][j] = 0.0f;

#pragma unroll
        for (int kc = 0; kc < 8; kc++) {
            uint32_t ah[2][4], bh[2][2];
#pragma unroll
            for (int m = 0; m < 2; m++) {
                uint32_t r = rA + m * 16;
                uint32_t u = 2 * kc + uA;
                LDSM4(ah[m], aB + r * 256 + (swz8(u, r) << 4));
            }
            {
                uint32_t u = 2 * kc + uB;
                uint32_t t[4];
                LDSM4(t, bB + rB * 256 + (swz8(u, rB) << 4));
                bh[0][0] = t[0]; bh[0][1] = t[1];
                bh[1][0] = t[2]; bh[1][1] = t[3];
            }
#pragma unroll
            for (int m = 0; m < 2; m++)
#pragma unroll
                for (int nf = 0; nf < 2; nf++)
                    MMA_F16(macc[m][nf], ah[m], bh[nf]);
        }

        // fold M[p] into Y_ab with compile-time ±1 coefficients (p unrolled)
        const int pi = p >> 2, pj = p & 3;
#pragma unroll
        for (int a = 0; a < 2; a++) {
            const float wa = (a == 0) ? AT0[pi] : AT1[pi];
#pragma unroll
            for (int b = 0; b < 2; b++) {
                const float wb = (b == 0) ? AT0[pj] : AT1[pj];
                const float c = wa * wb;
                if (c != 0.0f) {
#pragma unroll
                    for (int m = 0; m < 2; m++)
#pragma unroll
                        for (int nf = 0; nf < 2; nf++)
#pragma unroll
                            for (int j = 0; j < 4; j++)
                                accY[a][b][m][nf][j] = fmaf(c, macc[m][nf][j],
                                                            accY[a][b][m][nf][j]);
                }
            }
        }
        __syncthreads();
    }

    // Epilogue: bias + direct Y writes
#pragma unroll
    for (int m = 0; m < 2; m++) {
#pragma unroll
        for (int h = 0; h < 2; h++) {
            int o = o0 + m * 16 + (lane >> 2) + h * 8;
            float bv = bias[o];
#pragma unroll
            for (int nf = 0; nf < 2; nf++) {
#pragma unroll
                for (int d = 0; d < 2; d++) {
                    int t = jb + n0 + nf * 8 + (lane & 3) * 2 + d;
                    int n = t / TPI;
                    int r = t - n * TPI;
                    int ty = r / NT;
                    int tx = r - ty * NT;
                    float* yp = y + ((size_t)(n * OD + o) * HH + 2 * ty) * HH + 2 * tx;
                    int j = 2 * h + d;
                    float2 v0 = make_float2(accY[0][0][m][nf][j] + bv,
                                            accY[0][1][m][nf][j] + bv);
                    float2 v1 = make_float2(accY[1][0][m][nf][j] + bv,
                                            accY[1][1][m][nf][j] + bv);
                    *(float2*)yp = v0;
                    *(float2*)(yp + HH) = v1;
                }
            }
        }
    }
}

// ---------------- launch --------------------------------------------------------
extern "C" void kernel_launch(void* const* d_in, const int* in_sizes, int n_in,
                              void* d_out, int out_size) {
    const float* x = (const float*)d_in[0];
    const float* w = (const float*)d_in[1];
    const float* bias = (const float*)d_in[2];
    float* y = (float*)d_out;

    cudaFuncSetAttribute(k_fused, cudaFuncAttributeMaxDynamicSharedMemorySize, FUSE_SMEM);

    k_wt<<<128, 128>>>(w);
    k_fused<<<TILES / 32, 256, FUSE_SMEM>>>(x, bias, y);   // 1568 CTAs
}

// round 14
// speedup vs baseline: 1.2744x; 1.0198x over previous
#include <cuda_runtime.h>
#include <cuda_fp16.h>
#include <cstdint>

// Winograd F(2x2,3x3): N=16, C=128, O=128, H=W=112, pad=1
#define NB 16
#define CD 128
#define OD 128
#define HH 112
#define NT 56
#define TPI (NT*NT)            // 3136 tiles per image
#define TILES (NB*TPI)         // 50176 total tiles

// Scratch (allocation-free): U fp16 only. V lives in SMEM.
__device__ unsigned short g_Uh[16 * OD * 128];            // 512 KB U[p][o][c]

__device__ __forceinline__ uint32_t smem_to_u32(const void* p) {
    uint32_t a;
    asm("{ .reg .u64 t; cvta.to.shared.u64 t, %1; cvt.u32.u64 %0, t; }" : "=r"(a) : "l"(p));
    return a;
}

// ldmatrix x4 (sm_75+)
#define LDSM4(r, addr) \
    asm volatile("ldmatrix.sync.aligned.m8n8.x4.shared.b16 {%0,%1,%2,%3}, [%4];" \
        : "=r"((r)[0]), "=r"((r)[1]), "=r"((r)[2]), "=r"((r)[3]) : "r"(addr))

// fp16 HMMA with fp32 accumulate (sm_80+)
#define MMA_F16(d, a, b) \
    asm volatile("mma.sync.aligned.m16n8k16.row.col.f32.f16.f16.f32 " \
        "{%0,%1,%2,%3},{%4,%5,%6,%7},{%8,%9},{%0,%1,%2,%3};" \
        : "+f"((d)[0]), "+f"((d)[1]), "+f"((d)[2]), "+f"((d)[3]) \
        : "r"((a)[0]), "r"((a)[1]), "r"((a)[2]), "r"((a)[3]), \
          "r"((b)[0]), "r"((b)[1]))

// cp.async (sm_80+)
#define CP16(dst, src) \
    asm volatile("cp.async.cg.shared.global [%0], [%1], 16;" :: "r"(dst), "l"(src) : "memory")
#define CP_COMMIT() asm volatile("cp.async.commit_group;" ::: "memory")
#define CP_WAIT0()  asm volatile("cp.async.wait_group 0;" ::: "memory")

// 256B rows = 16x 16B units; swizzle keeps bit3, XORs low3 with row
__device__ __forceinline__ uint32_t swz8(uint32_t u, uint32_t row) {
    return (u & 8u) | ((u ^ row) & 7u);
}

// ---------------- K1: weight transform  U = G g G^T -> fp16 ------------------
__global__ void k_wt(const float* __restrict__ w) {
    int tid = blockIdx.x * 128 + threadIdx.x;   // 16384 threads: (c,o)
    int o = tid & 127;
    int c = tid >> 7;
    const float* g = w + ((size_t)o * CD + c) * 9;
    float gm[3][3];
#pragma unroll
    for (int i = 0; i < 3; i++)
#pragma unroll
        for (int j = 0; j < 3; j++) gm[i][j] = g[i * 3 + j];

    float t[4][3];
#pragma unroll
    for (int k = 0; k < 3; k++) {
        t[0][k] = gm[0][k];
        t[1][k] = 0.5f * (gm[0][k] + gm[1][k] + gm[2][k]);
        t[2][k] = 0.5f * (gm[0][k] - gm[1][k] + gm[2][k]);
        t[3][k] = gm[2][k];
    }
#pragma unroll
    for (int i = 0; i < 4; i++) {
        float u[4];
        u[0] = t[i][0];
        u[1] = 0.5f * (t[i][0] + t[i][1] + t[i][2]);
        u[2] = 0.5f * (t[i][0] - t[i][1] + t[i][2]);
        u[3] = t[i][2];
#pragma unroll
        for (int j = 0; j < 4; j++) {
            int p = i * 4 + j;
            g_Uh[((size_t)(p * OD + o)) * 128 + c] =
                __half_as_ushort(__float2half_rn(u[j]));
        }
    }
}

// ---------------- K2: fully fused transform + GEMM + output -------------------
// CTA: o=128 x tiles=32, 512 threads (16 warps: 8 o-groups x 2 t-groups,
// warp tile 16o x 16t -> accY 32 regs/thread, 4 warps/SMSP for latency hiding).
// Phase 1: V = BT d BT^T for all 16 p into SMEM (fp16, swizzled).
// Phase 2: loop p: M[p] = U[p]·V[p] (single fp16 MMA), fold into Y (AT coeffs).
// SMEM: A double-buffer 2x32KB @ 0, V 16 p-planes x 8KB @ 64KB. Total 192KB.
#define A_STG 32768
#define V_OFF 65536
#define FUSE_SMEM (V_OFF + 16 * 8192)   // 192 KB

__global__ void __launch_bounds__(512, 1) k_fused(const float* __restrict__ x,
                                                  const float* __restrict__ bias,
                                                  float* __restrict__ y) {
    extern __shared__ char sm[];
    const uint32_t base = smem_to_u32(sm);
    const int tid = threadIdx.x;
    const int lane = tid & 31;
    const int wid = tid >> 5;
    const int jb = blockIdx.x * 32;
    const int o0 = (wid & 7) * 16;    // 8 o-groups
    const int n0 = (wid >> 3) * 16;   // 2 t-groups

    // kick off A(p=0) staging; overlaps with the transform phase
    {
        const uint4* gA = (const uint4*)g_Uh;
#pragma unroll
        for (int i = 0; i < 4; i++) {
            int g = i * 512 + tid;                 // 2048 chunks (32KB)
            uint32_t row = (uint32_t)g >> 4, u = (uint32_t)g & 15;
            CP16(base + row * 256 + swz8(u, row) * 16, gA + g);
        }
        CP_COMMIT();
    }

    // ---- Phase 1: input transform into SMEM V[p][tile][c] fp16 ----
    // 2048 (c2, tl) tasks: c2 = channel pair 0..63, tl = tile 0..31.
#pragma unroll 1
    for (int it = 0; it < 4; it++) {
        int c2 = it * 16 + wid;      // 0..63
        int tl = lane;
        int tile = jb + tl;
        int n = tile / TPI;
        int r = tile - n * TPI;
        int ty = r / NT;
        int tx = r - ty * NT;
        int r0 = 2 * ty - 1, c0 = 2 * tx - 1;

        unsigned short h[2][16];
#pragma unroll
        for (int cc = 0; cc < 2; cc++) {
            int c = 2 * c2 + cc;
            const float* xp = x + ((size_t)(n * CD + c)) * (HH * HH);
            float d[4][4];
#pragma unroll
            for (int ii = 0; ii < 4; ii++) {
                int rr = r0 + ii;
                bool okr = ((unsigned)rr < HH);
#pragma unroll
                for (int jj = 0; jj < 4; jj++) {
                    int ccol = c0 + jj;
                    d[ii][jj] = (okr && (unsigned)ccol < HH) ? xp[rr * HH + ccol] : 0.0f;
                }
            }
            float t[4][4];
#pragma unroll
            for (int j = 0; j < 4; j++) {
                t[0][j] = d[0][j] - d[2][j];
                t[1][j] = d[1][j] + d[2][j];
                t[2][j] = d[2][j] - d[1][j];
                t[3][j] = d[1][j] - d[3][j];
            }
#pragma unroll
            for (int i = 0; i < 4; i++) {
                float v0 = t[i][0] - t[i][2];
                float v1 = t[i][1] + t[i][2];
                float v2 = t[i][2] - t[i][1];
                float v3 = t[i][1] - t[i][3];
                h[cc][i * 4 + 0] = __half_as_ushort(__float2half_rn(v0));
                h[cc][i * 4 + 1] = __half_as_ushort(__float2half_rn(v1));
                h[cc][i * 4 + 2] = __half_as_ushort(__float2half_rn(v2));
                h[cc][i * 4 + 3] = __half_as_ushort(__float2half_rn(v3));
            }
        }
        // write 16 p-planes: V[p][tl][c2 pair] (the layout the GEMM B expects)
        uint32_t woff = (uint32_t)tl * 256 + swz8((uint32_t)c2 >> 2, (uint32_t)tl) * 16
                        + ((uint32_t)c2 & 3) * 4;
#pragma unroll
        for (int p = 0; p < 16; p++) {
            uint32_t pk = (uint32_t)h[0][p] | ((uint32_t)h[1][p] << 16);
            *(uint32_t*)(sm + V_OFF + p * 8192 + woff) = pk;
        }
    }
    __syncthreads();

    // ---- Phase 2: GEMM + output-transform fold ----
    float accY[2][2][2][4];   // [a][b][nf][j] = 32 regs
#pragma unroll
    for (int a = 0; a < 2; a++)
#pragma unroll
        for (int b = 0; b < 2; b++)
#pragma unroll
            for (int nf = 0; nf < 2; nf++)
#pragma unroll
                for (int j = 0; j < 4; j++) accY[a][b][nf][j] = 0.0f;

    const uint32_t rA = (uint32_t)(o0 + (lane & 15));
    const uint32_t uA = (uint32_t)(lane >> 4);
    const uint32_t rB = (uint32_t)(n0 + (lane & 7) + ((lane & 16) >> 1));
    const uint32_t uB = (uint32_t)((lane >> 3) & 1);

    const float AT0[4] = {1.f, 1.f, 1.f, 0.f};
    const float AT1[4] = {0.f, 1.f, -1.f, -1.f};

#pragma unroll
    for (int p = 0; p < 16; p++) {
        CP_WAIT0();
        __syncthreads();

        if (p < 15) {   // stage A(p+1) into the other buffer
            uint32_t nb = base + (uint32_t)((p + 1) & 1) * A_STG;
            const uint4* gA = (const uint4*)(g_Uh + (size_t)(p + 1) * OD * 128);
#pragma unroll
            for (int i = 0; i < 4; i++) {
                int g = i * 512 + tid;
                uint32_t row = (uint32_t)g >> 4, u = (uint32_t)g & 15;
                CP16(nb + row * 256 + swz8(u, row) * 16, gA + g);
            }
            CP_COMMIT();
        }

        const uint32_t aB = base + (uint32_t)(p & 1) * A_STG;
        const uint32_t bB = base + V_OFF + (uint32_t)p * 8192;

        float macc[2][4];
#pragma unroll
        for (int nf = 0; nf < 2; nf++)
#pragma unroll
            for (int j = 0; j < 4; j++) macc[nf][j] = 0.0f;

#pragma unroll
        for (int kc = 0; kc < 8; kc++) {
            uint32_t ah[4], bh[2][2];
            {
                uint32_t u = 2 * kc + uA;
                LDSM4(ah, aB + rA * 256 + (swz8(u, rA) << 4));
            }
            {
                uint32_t u = 2 * kc + uB;
                uint32_t t[4];
                LDSM4(t, bB + rB * 256 + (swz8(u, rB) << 4));
                bh[0][0] = t[0]; bh[0][1] = t[1];
                bh[1][0] = t[2]; bh[1][1] = t[3];
            }
#pragma unroll
            for (int nf = 0; nf < 2; nf++)
                MMA_F16(macc[nf], ah, bh[nf]);
        }

        // fold M[p] into Y_ab with compile-time ±1 coefficients (p unrolled)
        const int pi = p >> 2, pj = p & 3;
#pragma unroll
        for (int a = 0; a < 2; a++) {
            const float wa = (a == 0) ? AT0[pi] : AT1[pi];
#pragma unroll
            for (int b = 0; b < 2; b++) {
                const float wb = (b == 0) ? AT0[pj] : AT1[pj];
                const float c = wa * wb;
                if (c != 0.0f) {
#pragma unroll
                    for (int nf = 0; nf < 2; nf++)
#pragma unroll
                        for (int j = 0; j < 4; j++)
                            accY[a][b][nf][j] = fmaf(c, macc[nf][j],
                                                     accY[a][b][nf][j]);
                }
            }
        }
        __syncthreads();
    }

    // Epilogue: bias + direct Y writes
#pragma unroll
    for (int h = 0; h < 2; h++) {
        int o = o0 + (lane >> 2) + h * 8;
        float bv = bias[o];
#pragma unroll
        for (int nf = 0; nf < 2; nf++) {
#pragma unroll
            for (int d = 0; d < 2; d++) {
                int t = jb + n0 + nf * 8 + (lane & 3) * 2 + d;
                int n = t / TPI;
                int r = t - n * TPI;
                int ty = r / NT;
                int tx = r - ty * NT;
                float* yp = y + ((size_t)(n * OD + o) * HH + 2 * ty) * HH + 2 * tx;
                int j = 2 * h + d;
                float2 v0 = make_float2(accY[0][0][nf][j] + bv,
                                        accY[0][1][nf][j] + bv);
                float2 v1 = make_float2(accY[1][0][nf][j] + bv,
                                        accY[1][1][nf][j] + bv);
                *(float2*)yp = v0;
                *(float2*)(yp + HH) = v1;
            }
        }
    }
}

// ---------------- launch --------------------------------------------------------
extern "C" void kernel_launch(void* const* d_in, const int* in_sizes, int n_in,
                              void* d_out, int out_size) {
    const float* x = (const float*)d_in[0];
    const float* w = (const float*)d_in[1];
    const float* bias = (const float*)d_in[2];
    float* y = (float*)d_out;

    cudaFuncSetAttribute(k_fused, cudaFuncAttributeMaxDynamicSharedMemorySize, FUSE_SMEM);

    k_wt<<<128, 128>>>(w);
    k_fused<<<TILES / 32, 512, FUSE_SMEM>>>(x, bias, y);   // 1568 CTAs
}

// round 15
// speedup vs baseline: 1.2873x; 1.0101x over previous
#include <cuda_runtime.h>
#include <cuda_fp16.h>
#include <cstdint>

// Winograd F(2x2,3x3): N=16, C=128, O=128, H=W=112, pad=1
#define NB 16
#define CD 128
#define OD 128
#define HH 112
#define NT 56
#define TPI (NT*NT)            // 3136 tiles per image
#define TILES (NB*TPI)         // 50176 total tiles

// Scratch (allocation-free): U fp16 only. V lives in SMEM.
__device__ unsigned short g_Uh[16 * OD * 128];            // 512 KB U[p][o][c]

__device__ __forceinline__ uint32_t smem_to_u32(const void* p) {
    uint32_t a;
    asm("{ .reg .u64 t; cvta.to.shared.u64 t, %1; cvt.u32.u64 %0, t; }" : "=r"(a) : "l"(p));
    return a;
}

// ldmatrix x4 (sm_75+)
#define LDSM4(r, addr) \
    asm volatile("ldmatrix.sync.aligned.m8n8.x4.shared.b16 {%0,%1,%2,%3}, [%4];" \
        : "=r"((r)[0]), "=r"((r)[1]), "=r"((r)[2]), "=r"((r)[3]) : "r"(addr))

// fp16 HMMA with fp32 accumulate (sm_80+)
#define MMA_F16(d, a, b) \
    asm volatile("mma.sync.aligned.m16n8k16.row.col.f32.f16.f16.f32 " \
        "{%0,%1,%2,%3},{%4,%5,%6,%7},{%8,%9},{%0,%1,%2,%3};" \
        : "+f"((d)[0]), "+f"((d)[1]), "+f"((d)[2]), "+f"((d)[3]) \
        : "r"((a)[0]), "r"((a)[1]), "r"((a)[2]), "r"((a)[3]), \
          "r"((b)[0]), "r"((b)[1]))

// cp.async (sm_80+)
#define CP16(dst, src) \
    asm volatile("cp.async.cg.shared.global [%0], [%1], 16;" :: "r"(dst), "l"(src) : "memory")
#define CP_COMMIT() asm volatile("cp.async.commit_group;" ::: "memory")
#define CP_WAIT0()  asm volatile("cp.async.wait_group 0;" ::: "memory")

// 256B rows = 16x 16B units; swizzle keeps bit3, XORs low3 with row
__device__ __forceinline__ uint32_t swz8(uint32_t u, uint32_t row) {
    return (u & 8u) | ((u ^ row) & 7u);
}

// ---------------- K1: weight transform  U = G g G^T -> fp16 ------------------
__global__ void k_wt(const float* __restrict__ w) {
    int tid = blockIdx.x * 128 + threadIdx.x;   // 16384 threads: (c,o)
    int o = tid & 127;
    int c = tid >> 7;
    const float* g = w + ((size_t)o * CD + c) * 9;
    float gm[3][3];
#pragma unroll
    for (int i = 0; i < 3; i++)
#pragma unroll
        for (int j = 0; j < 3; j++) gm[i][j] = g[i * 3 + j];

    float t[4][3];
#pragma unroll
    for (int k = 0; k < 3; k++) {
        t[0][k] = gm[0][k];
        t[1][k] = 0.5f * (gm[0][k] + gm[1][k] + gm[2][k]);
        t[2][k] = 0.5f * (gm[0][k] - gm[1][k] + gm[2][k]);
        t[3][k] = gm[2][k];
    }
#pragma unroll
    for (int i = 0; i < 4; i++) {
        float u[4];
        u[0] = t[i][0];
        u[1] = 0.5f * (t[i][0] + t[i][1] + t[i][2]);
        u[2] = 0.5f * (t[i][0] - t[i][1] + t[i][2]);
        u[3] = t[i][2];
#pragma unroll
        for (int j = 0; j < 4; j++) {
            int p = i * 4 + j;
            g_Uh[((size_t)(p * OD + o)) * 128 + c] =
                __half_as_ushort(__float2half_rn(u[j]));
        }
    }
}

// ---------------- K2: fully fused transform + GEMM + output -------------------
// CTA: o=128 x tiles=32, 256 threads. Phase 1: all 8 warps compute V into SMEM.
// Phase 2: warps 0-3 = consumers (warp tile 32o x 32t: 4 LDSM -> 8 MMA per kc),
//          warps 4-7 = helpers (stage A(p+1) via cp.async, overlapped with GEMM).
// One barrier per p. SMEM: A 2x32KB @ 0, V 16 x 8KB @ 64KB = 192 KB.
#define A_STG 32768
#define V_OFF 65536
#define FUSE_SMEM (V_OFF + 16 * 8192)   // 192 KB

__global__ void __launch_bounds__(256, 1) k_fused(const float* __restrict__ x,
                                                  const float* __restrict__ bias,
                                                  float* __restrict__ y) {
    extern __shared__ char sm[];
    const uint32_t base = smem_to_u32(sm);
    const int tid = threadIdx.x;
    const int lane = tid & 31;
    const int wid = tid >> 5;
    const int jb = blockIdx.x * 32;

    // Prologue: all 256 threads stage A(p=0) into buffer 0 (8 chunks each)
    {
        const uint4* gA = (const uint4*)g_Uh;
#pragma unroll
        for (int i = 0; i < 8; i++) {
            int g = i * 256 + tid;                 // 2048 chunks (32KB)
            uint32_t row = (uint32_t)g >> 4, u = (uint32_t)g & 15;
            CP16(base + row * 256 + swz8(u, row) * 16, gA + g);
        }
        CP_COMMIT();
    }

    // ---- Phase 1: input transform into SMEM V[p][tile][c] fp16 (all 8 warps) --
#pragma unroll 1
    for (int it = 0; it < 8; it++) {
        int c2 = it * 8 + wid;       // channel pair 0..63
        int tl = lane;
        int tile = jb + tl;
        int n = tile / TPI;
        int r = tile - n * TPI;
        int ty = r / NT;
        int tx = r - ty * NT;
        int r0 = 2 * ty - 1, c0 = 2 * tx - 1;

        unsigned short h[2][16];
#pragma unroll
        for (int cc = 0; cc < 2; cc++) {
            int c = 2 * c2 + cc;
            const float* xp = x + ((size_t)(n * CD + c)) * (HH * HH);
            float d[4][4];
#pragma unroll
            for (int ii = 0; ii < 4; ii++) {
                int rr = r0 + ii;
                bool okr = ((unsigned)rr < HH);
#pragma unroll
                for (int jj = 0; jj < 4; jj++) {
                    int ccol = c0 + jj;
                    d[ii][jj] = (okr && (unsigned)ccol < HH) ? xp[rr * HH + ccol] : 0.0f;
                }
            }
            float t[4][4];
#pragma unroll
            for (int j = 0; j < 4; j++) {
                t[0][j] = d[0][j] - d[2][j];
                t[1][j] = d[1][j] + d[2][j];
                t[2][j] = d[2][j] - d[1][j];
                t[3][j] = d[1][j] - d[3][j];
            }
#pragma unroll
            for (int i = 0; i < 4; i++) {
                float v0 = t[i][0] - t[i][2];
                float v1 = t[i][1] + t[i][2];
                float v2 = t[i][2] - t[i][1];
                float v3 = t[i][1] - t[i][3];
                h[cc][i * 4 + 0] = __half_as_ushort(__float2half_rn(v0));
                h[cc][i * 4 + 1] = __half_as_ushort(__float2half_rn(v1));
                h[cc][i * 4 + 2] = __half_as_ushort(__float2half_rn(v2));
                h[cc][i * 4 + 3] = __half_as_ushort(__float2half_rn(v3));
            }
        }
        uint32_t woff = (uint32_t)tl * 256 + swz8((uint32_t)c2 >> 2, (uint32_t)tl) * 16
                        + ((uint32_t)c2 & 3) * 4;
#pragma unroll
        for (int p = 0; p < 16; p++) {
            uint32_t pk = (uint32_t)h[0][p] | ((uint32_t)h[1][p] << 16);
            *(uint32_t*)(sm + V_OFF + p * 8192 + woff) = pk;
        }
    }
    CP_WAIT0();          // A(0) landed (every thread issued its own chunks)
    __syncthreads();     // V + A(0) visible

    // ---- Phase 2: warp-specialized GEMM + output-transform fold ----
    const bool consumer = (wid < 4);
    const int o0 = wid * 32;                 // consumer o-group (wid 0-3)

    float accY[2][2][2][4][4];   // [a][b][m][nf][j] = 128 regs (consumers only)
#pragma unroll
    for (int a = 0; a < 2; a++)
#pragma unroll
        for (int b = 0; b < 2; b++)
#pragma unroll
            for (int m = 0; m < 2; m++)
#pragma unroll
                for (int nf = 0; nf < 4; nf++)
#pragma unroll
                    for (int j = 0; j < 4; j++) accY[a][b][m][nf][j] = 0.0f;

    const uint32_t rA = (uint32_t)(o0 + (lane & 15));
    const uint32_t uA = (uint32_t)(lane >> 4);
    const uint32_t rB = (uint32_t)((lane & 7) + ((lane & 16) >> 1));
    const uint32_t uB = (uint32_t)((lane >> 3) & 1);

    const float AT0[4] = {1.f, 1.f, 1.f, 0.f};
    const float AT1[4] = {0.f, 1.f, -1.f, -1.f};

#pragma unroll 1
    for (int p = 0; p < 16; p++) {
        if (!consumer) {
            // helpers: stage A(p+1) into the other buffer, concurrent with GEMM
            if (p < 15) {
                uint32_t nb = base + (uint32_t)((p + 1) & 1) * A_STG;
                const uint4* gA = (const uint4*)(g_Uh + (size_t)(p + 1) * OD * 128);
                int htid = tid - 128;
#pragma unroll
                for (int i = 0; i < 16; i++) {
                    int g = i * 128 + htid;
                    uint32_t row = (uint32_t)g >> 4, u = (uint32_t)g & 15;
                    CP16(nb + row * 256 + swz8(u, row) * 16, gA + g);
                }
                CP_COMMIT();
                CP_WAIT0();
            }
        } else {
            const uint32_t aB = base + (uint32_t)(p & 1) * A_STG;
            const uint32_t bB = base + V_OFF + (uint32_t)p * 8192;

            float macc[2][4][4];
#pragma unroll
            for (int m = 0; m < 2; m++)
#pragma unroll
                for (int nf = 0; nf < 4; nf++)
#pragma unroll
                    for (int j = 0; j < 4; j++) macc[m][nf][j] = 0.0f;

#pragma unroll
            for (int kc = 0; kc < 8; kc++) {
                uint32_t ah[2][4], bh[4][2];
#pragma unroll
                for (int m = 0; m < 2; m++) {
                    uint32_t r = rA + m * 16;
                    uint32_t u = 2 * kc + uA;
                    LDSM4(ah[m], aB + r * 256 + (swz8(u, r) << 4));
                }
#pragma unroll
                for (int q = 0; q < 2; q++) {
                    uint32_t r = rB + q * 16;
                    uint32_t u = 2 * kc + uB;
                    uint32_t t[4];
                    LDSM4(t, bB + r * 256 + (swz8(u, r) << 4));
                    bh[2 * q][0] = t[0]; bh[2 * q][1] = t[1];
                    bh[2 * q + 1][0] = t[2]; bh[2 * q + 1][1] = t[3];
                }
#pragma unroll
                for (int m = 0; m < 2; m++)
#pragma unroll
                    for (int nf = 0; nf < 4; nf++)
                        MMA_F16(macc[m][nf], ah[m], bh[nf]);
            }

            // fold M[p] into Y_ab with compile-time ±1 coefficients
            const int pi = p >> 2, pj = p & 3;
#pragma unroll
            for (int a = 0; a < 2; a++) {
                const float wa = (a == 0) ? AT0[pi] : AT1[pi];
#pragma unroll
                for (int b = 0; b < 2; b++) {
                    const float wb = (b == 0) ? AT0[pj] : AT1[pj];
                    const float c = wa * wb;
                    if (c != 0.0f) {
#pragma unroll
                        for (int m = 0; m < 2; m++)
#pragma unroll
                            for (int nf = 0; nf < 4; nf++)
#pragma unroll
                                for (int j = 0; j < 4; j++)
                                    accY[a][b][m][nf][j] = fmaf(c, macc[m][nf][j],
                                                                accY[a][b][m][nf][j]);
                    }
                }
            }
        }
        __syncthreads();   // one barrier per p: A(p+1) visible; buf(p) consumed
    }

    // Epilogue: consumers write Y (bias + direct stores)
    if (consumer) {
#pragma unroll
        for (int m = 0; m < 2; m++) {
#pragma unroll
            for (int h = 0; h < 2; h++) {
                int o = o0 + m * 16 + (lane >> 2) + h * 8;
                float bv = bias[o];
#pragma unroll
                for (int nf = 0; nf < 4; nf++) {
#pragma unroll
                    for (int d = 0; d < 2; d++) {
                        int t = jb + nf * 8 + (lane & 3) * 2 + d;
                        int n = t / TPI;
                        int r = t - n * TPI;
                        int ty = r / NT;
                        int tx = r - ty * NT;
                        float* yp = y + ((size_t)(n * OD + o) * HH + 2 * ty) * HH + 2 * tx;
                        int j = 2 * h + d;
                        float2 v0 = make_float2(accY[0][0][m][nf][j] + bv,
                                                accY[0][1][m][nf][j] + bv);
                        float2 v1 = make_float2(accY[1][0][m][nf][j] + bv,
                                                accY[1][1][m][nf][j] + bv);
                        *(float2*)yp = v0;
                        *(float2*)(yp + HH) = v1;
                    }
                }
            }
        }
    }
}

// ---------------- launch --------------------------------------------------------
extern "C" void kernel_launch(void* const* d_in, const int* in_sizes, int n_in,
                              void* d_out, int out_size) {
    const float* x = (const float*)d_in[0];
    const float* w = (const float*)d_in[1];
    const float* bias = (const float*)d_in[2];
    float* y = (float*)d_out;

    cudaFuncSetAttribute(k_fused, cudaFuncAttributeMaxDynamicSharedMemorySize, FUSE_SMEM);

    k_wt<<<128, 128>>>(w);
    k_fused<<<TILES / 32, 256, FUSE_SMEM>>>(x, bias, y);   // 1568 CTAs
}